// round 13
// baseline (speedup 1.0000x reference)
#include <cuda_runtime.h>
#include <cuda_bf16.h>
#include <math.h>
#include <stdint.h>

static constexpr int B_   = 64;
static constexpr int HENC = 512;
static constexpr int E_   = 512;
static constexpr int H_   = 1024;
static constexpr int V_   = 32000;
static constexpr int T_   = 64;
static constexpr int SOS  = 1;
static constexpr int EOS  = 2;
static constexpr int CAND_CAP = 2048;
static constexpr int GRID_STEP = 125;      // CTAs in the fused step kernel

// ---------------- persistent device state ----------------
__device__ float g_flat[B_ * 2 * HENC];
__device__ float g_h[B_ * H_];
__device__ float g_Gc[B_ * 3 * H_];
__device__ float g_GcT[3 * H_ * B_];
__device__ float g_giT[3 * H_ * B_];
__device__ float g_ghT[3 * H_ * B_];
__device__ int   g_inp[B_];
__device__ int   g_fin[B_];
__device__ float g_hnorm[2 * B_];            // per-batch {‖h_b‖², ‖h_b−h_hi‖²}
__device__ unsigned g_nmax[2];               // {max ‖Wh_row‖, max ‖Wl_row‖} float bits
__device__ unsigned g_amaxv[B_];             // per-batch max approx logit (ordered bits)
__device__ float g_applog[(size_t)B_ * V_];  // approx logits [batch][vocab]

// grid-barrier state (flag monotonic across launches/replays; ctr self-resets)
__device__ unsigned g_barctr  = 0;
__device__ unsigned g_barflag = 0;

// bf16 split weights / activations
__device__ __nv_bfloat16 g_WihE_hi[3 * H_ * E_];
__device__ __nv_bfloat16 g_WihE_lo[3 * H_ * E_];
__device__ __nv_bfloat16 g_Whh_hi[3 * H_ * H_];
__device__ __nv_bfloat16 g_Whh_lo[3 * H_ * H_];
__device__ __nv_bfloat16 g_Wout_hi[(size_t)V_ * H_];
__device__ __nv_bfloat16 g_x_hi[B_ * E_];
__device__ __nv_bfloat16 g_x_lo[B_ * E_];
__device__ __nv_bfloat16 g_h_hi[B_ * H_];
__device__ __nv_bfloat16 g_h_lo[B_ * H_];

// ---------------------------------------------------------------------------
__device__ __forceinline__ uint32_t smem_u32(const void* p) {
    uint32_t a;
    asm("{ .reg .u64 t; cvta.to.shared.u64 t, %1; cvt.u32.u64 %0, t; }"
        : "=r"(a) : "l"(p));
    return a;
}

__device__ __forceinline__ void cp16(uint32_t dst, const void* src) {
    asm volatile("cp.async.cg.shared.global [%0], [%1], 16;"
                 :: "r"(dst), "l"(src));
}
#define CP_COMMIT() asm volatile("cp.async.commit_group;")
#define CP_WAIT(n)  asm volatile("cp.async.wait_group %0;" :: "n"(n))

#define LDMX4(R0, R1, R2, R3, ADDR)                                           \
    asm volatile("ldmatrix.sync.aligned.m8n8.x4.shared.b16 {%0,%1,%2,%3}, [%4];" \
                 : "=r"(R0), "=r"(R1), "=r"(R2), "=r"(R3) : "r"(ADDR))

#define MMA16816(D, A, Bv)                                                    \
    asm volatile("mma.sync.aligned.m16n8k16.row.col.f32.bf16.bf16.f32 "       \
                 "{%0,%1,%2,%3},{%4,%5,%6,%7},{%8,%9},{%0,%1,%2,%3};"          \
                 : "+f"(D[0]), "+f"(D[1]), "+f"(D[2]), "+f"(D[3])              \
                 : "r"(A[0]), "r"(A[1]), "r"(A[2]), "r"(A[3]),                 \
                   "r"(Bv[0]), "r"(Bv[1]))

__device__ __forceinline__ unsigned ordbits(float v) {
    unsigned u = __float_as_uint(v);
    return (u & 0x80000000u) ? ~u : (u | 0x80000000u);
}
__device__ __forceinline__ float ordfloat(unsigned u) {
    return (u & 0x80000000u) ? __uint_as_float(u ^ 0x80000000u)
                             : __uint_as_float(~u);
}
__device__ __forceinline__ unsigned long long packkey(float v, int row) {
    return ((unsigned long long)ordbits(v) << 32) |
           (unsigned)(0xFFFFFFFFu - (unsigned)row);
}

// grid barrier: snapshot-flag + self-resetting counter (replay-safe)
__device__ __forceinline__ void gbar() {
    __threadfence();
    __syncthreads();
    if (threadIdx.x == 0) {
        unsigned snap = *(volatile unsigned*)&g_barflag;
        unsigned v = atomicAdd(&g_barctr, 1);
        if (v == gridDim.x - 1) {
            atomicSub(&g_barctr, gridDim.x);
            __threadfence();
            atomicAdd(&g_barflag, 1);
        } else {
            while (*(volatile unsigned*)&g_barflag == snap) __nanosleep(64);
        }
        __threadfence();
    }
    __syncthreads();
}

// ---------------------------------------------------------------------------
static constexpr int SROW = 40;
template <int SPLITS, int MTILES>
__device__ __forceinline__ uint32_t abuf_off(int buf, int split) {
    return (uint32_t)(buf * (SPLITS * 10240 * MTILES) + split * (10240 * MTILES));
}
template <int SPLITS, int MTILES>
__device__ __forceinline__ uint32_t bbuf_off(int buf, int split) {
    return (uint32_t)(SPLITS * 20480 * MTILES + buf * (SPLITS * 5120) + split * 5120);
}
static constexpr int TCSMEM = 61440;   // max of gates (2,1) and logits (1,2) layouts

// ---------------------------------------------------------------------------
// Core GEMM: D = A[M,K] @ B[64,K]^T, (128*MTILES)x64 tile/CTA, 8 warps,
// cp.async 2-stage.  SPLITS=2: 3-product bf16 split;  SPLITS=1: hi-only.
// MODE 0: D[r*64+c] = acc + bias[r] + addT[r*64+c]
// MODE 2: g_applog[c*V + r] = acc + bias[r]; per-column max -> s_cmax
// ---------------------------------------------------------------------------
template <int MODE, int SPLITS, int MTILES>
__device__ __forceinline__ void mma_core(
    const __nv_bfloat16* __restrict__ Ah, const __nv_bfloat16* __restrict__ Al,
    const __nv_bfloat16* __restrict__ Bh, const __nv_bfloat16* __restrict__ Bl,
    int K, const float* __restrict__ bias, const float* __restrict__ addT,
    float* __restrict__ D, int m0, unsigned* s_cmax)
{
    extern __shared__ __align__(16) char smem[];
    const uint32_t sb = smem_u32(smem);
    const int tid = threadIdx.x, lane = tid & 31, warp = tid >> 5;
    const int mwbase = warp * 16 * MTILES;

    float acc[MTILES][8][4];
#pragma unroll
    for (int tt = 0; tt < MTILES; tt++)
#pragma unroll
        for (int f = 0; f < 8; f++)
#pragma unroll
            for (int j = 0; j < 4; j++) acc[tt][f][j] = 0.f;

    const int a_sub  = ((lane >> 3) & 1) * 8 + (lane & 7);
    const int a_koff = (lane >> 4) * 8;
    const int b_row  = (lane >> 4) * 8 + (lane & 7);
    const int b_koff = ((lane >> 3) & 1) * 8;

    const int nch = K >> 5;

    auto stage = [&](int kc, int buf) {
        const int kb = kc << 5;
#pragma unroll
        for (int i = 0; i < 2 * MTILES; i++) {
            int id = tid + (i << 8);
            int r = id >> 2, c = id & 3;
            uint32_t so = (uint32_t)(r * 80 + c * 16);
            const size_t go = (size_t)(m0 + r) * K + kb + c * 8;
            cp16(sb + abuf_off<SPLITS, MTILES>(buf, 0) + so, Ah + go);
            if (SPLITS == 2) cp16(sb + abuf_off<SPLITS, MTILES>(buf, 1) + so, Al + go);
        }
        {
            int r = tid >> 2, c = tid & 3;
            uint32_t so = (uint32_t)(r * 80 + c * 16);
            const size_t go = (size_t)r * K + kb + c * 8;
            cp16(sb + bbuf_off<SPLITS, MTILES>(buf, 0) + so, Bh + go);
            if (SPLITS == 2) cp16(sb + bbuf_off<SPLITS, MTILES>(buf, 1) + so, Bl + go);
        }
    };

    stage(0, 0);
    CP_COMMIT();

    for (int kc = 0; kc < nch; kc++) {
        const int cur = kc & 1;
        if (kc + 1 < nch) {
            stage(kc + 1, cur ^ 1);
            CP_COMMIT();
            CP_WAIT(1);
        } else {
            CP_WAIT(0);
        }
        __syncthreads();

#pragma unroll
        for (int ks = 0; ks < 2; ks++) {
            const int kk = ks * 16;
            uint32_t bh[8][2], bl[8][2];
#pragma unroll
            for (int p = 0; p < 4; p++) {
                uint32_t ad = sb + bbuf_off<SPLITS, MTILES>(cur, 0) +
                              (uint32_t)(((p * 16 + b_row) * SROW + kk + b_koff) * 2);
                LDMX4(bh[2 * p][0], bh[2 * p][1], bh[2 * p + 1][0], bh[2 * p + 1][1], ad);
                if (SPLITS == 2) {
                    ad = sb + bbuf_off<SPLITS, MTILES>(cur, 1) +
                         (uint32_t)(((p * 16 + b_row) * SROW + kk + b_koff) * 2);
                    LDMX4(bl[2 * p][0], bl[2 * p][1], bl[2 * p + 1][0], bl[2 * p + 1][1], ad);
                }
            }
#pragma unroll
            for (int tt = 0; tt < MTILES; tt++) {
                const int a_row = mwbase + tt * 16 + a_sub;
                uint32_t ah[4], al[4];
                uint32_t ad = sb + abuf_off<SPLITS, MTILES>(cur, 0) +
                              (uint32_t)((a_row * SROW + kk + a_koff) * 2);
                LDMX4(ah[0], ah[1], ah[2], ah[3], ad);
                if (SPLITS == 2) {
                    ad = sb + abuf_off<SPLITS, MTILES>(cur, 1) +
                         (uint32_t)((a_row * SROW + kk + a_koff) * 2);
                    LDMX4(al[0], al[1], al[2], al[3], ad);
                }
#pragma unroll
                for (int f = 0; f < 8; f++) {
                    MMA16816(acc[tt][f], ah, bh[f]);
                    if (SPLITS == 2) {
                        MMA16816(acc[tt][f], ah, bl[f]);
                        MMA16816(acc[tt][f], al, bh[f]);
                    }
                }
            }
        }
        __syncthreads();
    }

    const int g  = lane >> 2;
    const int tq = lane & 3;

    if (MODE == 0) {
#pragma unroll
        for (int tt = 0; tt < MTILES; tt++) {
            const int r0 = m0 + mwbase + tt * 16 + g;
            const int r1 = r0 + 8;
            const float b0v = bias ? bias[r0] : 0.f;
            const float b1v = bias ? bias[r1] : 0.f;
#pragma unroll
            for (int f = 0; f < 8; f++) {
#pragma unroll
                for (int j = 0; j < 2; j++) {
                    const int c = f * 8 + tq * 2 + j;
                    float v0 = acc[tt][f][j]     + b0v;
                    float v1 = acc[tt][f][2 + j] + b1v;
                    if (addT) {
                        v0 += addT[(size_t)r0 * 64 + c];
                        v1 += addT[(size_t)r1 * 64 + c];
                    }
                    D[(size_t)r0 * 64 + c] = v0;
                    D[(size_t)r1 * 64 + c] = v1;
                }
            }
        }
    } else {
        unsigned cm[16];
#pragma unroll
        for (int q = 0; q < 16; q++) cm[q] = 0u;
#pragma unroll
        for (int tt = 0; tt < MTILES; tt++) {
            const int r0 = m0 + mwbase + tt * 16 + g;
            const int r1 = r0 + 8;
            const float b0v = bias[r0];
            const float b1v = bias[r1];
#pragma unroll
            for (int f = 0; f < 8; f++) {
#pragma unroll
                for (int j = 0; j < 2; j++) {
                    const int c = f * 8 + tq * 2 + j;
                    float v0 = acc[tt][f][j]     + b0v;
                    float v1 = acc[tt][f][2 + j] + b1v;
                    g_applog[(size_t)c * V_ + r0] = v0;
                    g_applog[(size_t)c * V_ + r1] = v1;
                    unsigned u = ordbits(v0), w = ordbits(v1);
                    unsigned m = (u > w) ? u : w;
                    if (m > cm[f * 2 + j]) cm[f * 2 + j] = m;
                }
            }
        }
        // reduce over the 8 lanes sharing tq (rows), then to smem per column
#pragma unroll
        for (int s = 4; s <= 16; s <<= 1)
#pragma unroll
            for (int q = 0; q < 16; q++) {
                unsigned o = __shfl_xor_sync(0xffffffffu, cm[q], s);
                if (o > cm[q]) cm[q] = o;
            }
        if (lane < 4) {
#pragma unroll
            for (int f = 0; f < 8; f++)
#pragma unroll
                for (int j = 0; j < 2; j++)
                    atomicMax(&s_cmax[f * 8 + lane * 2 + j], cm[f * 2 + j]);
        }
    }
}

// ---------------------------------------------------------------------------
// One decode step, fully fused. grid = 125 CTAs (all resident).
// P1: gates MMAs (CTAs 0..47) | P2: GRU gates elementwise (all)
// P3: logits MMA + local max (all) | P4: rescore + token + next-x (CTAs 0..63)
// ---------------------------------------------------------------------------
__global__ void __launch_bounds__(256) k_step(
    const float* __restrict__ b_hh, const float* __restrict__ out_b,
    const float* __restrict__ out_w, const float* __restrict__ emb,
    float* __restrict__ out_tok, int t)
{
    __shared__ float s_nrm[2 * B_];
    __shared__ unsigned s_cmax[B_];
    __shared__ float sh_h[H_];
    __shared__ int cand[CAND_CAP];
    __shared__ int cnt;
    __shared__ unsigned long long bestkey;
    __shared__ int s_tok;

    const int bid = blockIdx.x;
    const int tid = threadIdx.x, lane = tid & 31, warp = tid >> 5;

    // ---- Phase 1: gates MMAs ----
    if (bid < 24)
        mma_core<0, 2, 1>(g_WihE_hi, g_WihE_lo, g_x_hi, g_x_lo, E_,
                          nullptr, g_GcT, g_giT, bid * 128, nullptr);
    else if (bid < 48)
        mma_core<0, 2, 1>(g_Whh_hi, g_Whh_lo, g_h_hi, g_h_lo, H_,
                          b_hh, nullptr, g_ghT, (bid - 24) * 128, nullptr);
    gbar();

    // ---- Phase 2: GRU gate elementwise + h split + per-batch norms ----
    if (tid < 2 * B_) s_nrm[tid] = 0.f;
    __syncthreads();
    for (int idx = bid * 256 + tid; idx < B_ * H_; idx += GRID_STEP * 256) {
        int b = idx & (B_ - 1);
        int i = idx >> 6;
        float ir  = g_giT[(size_t)i * 64 + b];
        float iz  = g_giT[(size_t)(H_ + i) * 64 + b];
        float in_ = g_giT[(size_t)(2 * H_ + i) * 64 + b];
        float hr  = g_ghT[(size_t)i * 64 + b];
        float hz  = g_ghT[(size_t)(H_ + i) * 64 + b];
        float hn  = g_ghT[(size_t)(2 * H_ + i) * 64 + b];
        float r = 1.f / (1.f + expf(-(ir + hr)));
        float z = 1.f / (1.f + expf(-(iz + hz)));
        float n = tanhf(in_ + r * hn);
        size_t hidx = (size_t)b * H_ + i;
        float h = g_h[hidx];
        float hnew = (1.f - z) * n + z * h;
        g_h[hidx] = hnew;
        __nv_bfloat16 hh = __float2bfloat16(hnew);
        g_h_hi[hidx] = hh;
        float res = hnew - __bfloat162float(hh);
        g_h_lo[hidx] = __float2bfloat16(res);
        atomicAdd(&s_nrm[b], hnew * hnew);
        atomicAdd(&s_nrm[B_ + b], res * res);
    }
    __syncthreads();
    if (tid < 2 * B_ && s_nrm[tid] != 0.f) atomicAdd(&g_hnorm[tid], s_nrm[tid]);
    if (tid < B_) s_cmax[tid] = 0u;
    gbar();

    // ---- Phase 3: logits MMA (hi-only) + per-column local max ----
    mma_core<2, 1, 2>(g_Wout_hi, nullptr, g_h_hi, nullptr, H_,
                      out_b, nullptr, nullptr, bid * 256, s_cmax);
    __syncthreads();
    if (tid < B_) atomicMax(&g_amaxv[tid], s_cmax[tid]);
    gbar();

    // ---- Phase 4: rescore + token + next-x embed (CTAs 0..63) ----
    if (bid >= B_) return;
    const int b = bid;
    const float* ap = g_applog + (size_t)b * V_;

    for (int i = tid; i < H_; i += 256) sh_h[i] = g_h[(size_t)b * H_ + i];
    if (tid == 0) { cnt = 0; bestkey = 0ULL; }
    __syncthreads();

    const float A   = ordfloat(g_amaxv[b]);
    const float nh  = sqrtf(g_hnorm[b]);
    const float nhl = sqrtf(g_hnorm[B_ + b]);
    const float nwh = __uint_as_float(g_nmax[0]);
    const float nwl = __uint_as_float(g_nmax[1]);
    const float eps = 2.f * (nwl * nh + nwh * nhl) + 0.1f;
    const float thresh = A - eps;

    for (int r = tid; r < V_; r += 256) {
        if (ap[r] >= thresh) {
            int i = atomicAdd(&cnt, 1);
            if (i < CAND_CAP) cand[i] = r;
        }
    }
    __syncthreads();

    if (cnt <= CAND_CAP) {
        const int nc = cnt;
        for (int ci = warp; ci < nc; ci += 8) {
            const int r = cand[ci];
            float s = 0.f;
            for (int k = lane; k < H_; k += 32)
                s += out_w[(size_t)r * H_ + k] * sh_h[k];
#pragma unroll
            for (int sft = 16; sft > 0; sft >>= 1)
                s += __shfl_xor_sync(0xffffffffu, s, sft);
            if (lane == 0)
                atomicMax(&bestkey, packkey(s + out_b[r], r));
        }
    } else {
        for (int r = warp; r < V_; r += 8) {
            float s = 0.f;
            for (int k = lane; k < H_; k += 32)
                s += out_w[(size_t)r * H_ + k] * sh_h[k];
#pragma unroll
            for (int sft = 16; sft > 0; sft >>= 1)
                s += __shfl_xor_sync(0xffffffffu, s, sft);
            if (lane == 0)
                atomicMax(&bestkey, packkey(s + out_b[r], r));
        }
    }
    __syncthreads();

    if (tid == 0) {
        int tok = (int)(0xFFFFFFFFu - (unsigned)(bestkey & 0xFFFFFFFFull));
        out_tok[b * T_ + t] = (float)tok;
        int fin = g_fin[b] | (tok == EOS);
        g_fin[b] = fin;
        int ninp = fin ? EOS : tok;
        g_inp[b] = ninp;
        s_tok = ninp;
        g_amaxv[b] = 0u;                      // reset for next step
    }
    __syncthreads();

    const int ninp = s_tok;
    for (int k = tid; k < E_; k += 256) {
        float v = emb[(size_t)ninp * E_ + k];
        __nv_bfloat16 h = __float2bfloat16(v);
        g_x_hi[b * E_ + k] = h;
        g_x_lo[b * E_ + k] = __float2bfloat16(v - __bfloat162float(h));
    }
    if (tid < 2) g_hnorm[tid * B_ + b] = 0.f;  // reset for next step
}

// ---------------------------------------------------------------------------
__global__ void k_setup(const float* __restrict__ enc) {
    int idx = blockIdx.x * blockDim.x + threadIdx.x;
    if (idx < B_ * 2 * HENC) {
        int b = idx / (2 * HENC);
        int k = idx % (2 * HENC);
        float v = (k < HENC) ? enc[b * HENC + k]
                             : enc[B_ * HENC + b * HENC + (k - HENC)];
        g_flat[idx] = v;
    }
    if (idx < B_) { g_inp[idx] = SOS; g_fin[idx] = 0; g_amaxv[idx] = 0u; }
    if (idx < 2)  { g_nmax[idx] = 0u; }
}

__global__ void __launch_bounds__(256) k_gemm(
    const float* __restrict__ A, int lda,
    const float* __restrict__ W, int ldw, int woff, int K,
    const float* __restrict__ bias, float* __restrict__ C, int ldc)
{
    __shared__ float As[32][68];
    __shared__ float Ws[32][68];
    const int tid = threadIdx.x;
    const int tx = tid & 15, ty = tid >> 4;
    const int n0 = blockIdx.x * 64;
    float acc[4][4] = {};

    for (int k0 = 0; k0 < K; k0 += 32) {
#pragma unroll
        for (int it = 0; it < 2; it++) {
            int idx = tid + it * 256;
            int row = idx >> 3;
            int kq  = (idx & 7) << 2;
            float4 v = *(const float4*)(A + (size_t)row * lda + k0 + kq);
            As[kq][row] = v.x; As[kq + 1][row] = v.y;
            As[kq + 2][row] = v.z; As[kq + 3][row] = v.w;
            float4 u = *(const float4*)(W + (size_t)(n0 + row) * ldw + woff + k0 + kq);
            Ws[kq][row] = u.x; Ws[kq + 1][row] = u.y;
            Ws[kq + 2][row] = u.z; Ws[kq + 3][row] = u.w;
        }
        __syncthreads();
#pragma unroll
        for (int k = 0; k < 32; k++) {
            float4 a = *(const float4*)&As[k][ty << 2];
            float4 w = *(const float4*)&Ws[k][tx << 2];
            acc[0][0] += a.x * w.x; acc[0][1] += a.x * w.y; acc[0][2] += a.x * w.z; acc[0][3] += a.x * w.w;
            acc[1][0] += a.y * w.x; acc[1][1] += a.y * w.y; acc[1][2] += a.y * w.z; acc[1][3] += a.y * w.w;
            acc[2][0] += a.z * w.x; acc[2][1] += a.z * w.y; acc[2][2] += a.z * w.z; acc[2][3] += a.z * w.w;
            acc[3][0] += a.w * w.x; acc[3][1] += a.w * w.y; acc[3][2] += a.w * w.z; acc[3][3] += a.w * w.w;
        }
        __syncthreads();
    }
#pragma unroll
    for (int i = 0; i < 4; i++) {
        int row = (ty << 2) + i;
#pragma unroll
        for (int j = 0; j < 4; j++) {
            int col = n0 + (tx << 2) + j;
            float v = acc[i][j];
            if (bias) v += bias[col];
            C[(size_t)row * ldc + col] = v;
        }
    }
}

__global__ void k_splitw(const float* __restrict__ src, int ld, int coloff, int cols,
                         __nv_bfloat16* __restrict__ hi, __nv_bfloat16* __restrict__ lo,
                         int n)
{
    int idx = blockIdx.x * blockDim.x + threadIdx.x;
    if (idx >= n) return;
    int r = idx / cols, c = idx % cols;
    float v = src[(size_t)r * ld + coloff + c];
    __nv_bfloat16 h = __float2bfloat16(v);
    hi[idx] = h;
    if (lo) lo[idx] = __float2bfloat16(v - __bfloat162float(h));
}

__global__ void k_split_h0() {
    int idx = blockIdx.x * blockDim.x + threadIdx.x;
    if (idx >= B_ * H_) return;
    float v = g_h[idx];
    __nv_bfloat16 h = __float2bfloat16(v);
    g_h_hi[idx] = h;
    g_h_lo[idx] = __float2bfloat16(v - __bfloat162float(h));
}

__global__ void k_mk_gcT() {
    int idx = blockIdx.x * blockDim.x + threadIdx.x;
    if (idx >= 3 * H_ * B_) return;
    int r = idx >> 6, c = idx & 63;
    g_GcT[idx] = g_Gc[(size_t)c * (3 * H_) + r];
}

__global__ void k_wnorms(const float* __restrict__ out_w) {
    int r = blockIdx.x * 8 + (threadIdx.x >> 5);
    int lane = threadIdx.x & 31;
    if (r >= V_) return;
    float sh = 0.f, sl = 0.f;
    for (int k = lane; k < H_; k += 32) {
        float w  = out_w[(size_t)r * H_ + k];
        float wh = __bfloat162float(g_Wout_hi[(size_t)r * H_ + k]);
        float wl = w - wh;
        sh += wh * wh;
        sl += wl * wl;
    }
#pragma unroll
    for (int s = 16; s > 0; s >>= 1) {
        sh += __shfl_xor_sync(0xffffffffu, sh, s);
        sl += __shfl_xor_sync(0xffffffffu, sl, s);
    }
    if (lane == 0) {
        atomicMax(&g_nmax[0], __float_as_uint(sqrtf(sh)));
        atomicMax(&g_nmax[1], __float_as_uint(sqrtf(sl)));
    }
}

// initial x split (SOS) + hnorm reset — used once before the loop
__global__ void k_split_x(const float* __restrict__ emb) {
    int idx = blockIdx.x * blockDim.x + threadIdx.x;
    if (idx < 2 * B_) g_hnorm[idx] = 0.f;
    if (idx >= B_ * E_) return;
    int b = idx >> 9;
    int k = idx & (E_ - 1);
    float v = emb[(size_t)g_inp[b] * E_ + k];
    __nv_bfloat16 h = __float2bfloat16(v);
    g_x_hi[idx] = h;
    g_x_lo[idx] = __float2bfloat16(v - __bfloat162float(h));
}

__global__ void k_writeh(float* __restrict__ out_h) {
    int idx = blockIdx.x * blockDim.x + threadIdx.x;
    if (idx < B_ * H_) out_h[idx] = g_h[idx];
}

// ---------------------------------------------------------------------------
extern "C" void kernel_launch(void* const* d_in, const int* in_sizes, int n_in,
                              void* d_out, int out_size) {
    const float* enc   = (const float*)d_in[0];
    const float* emb   = (const float*)d_in[1];
    const float* Wh_w  = (const float*)d_in[2];
    const float* Wh_b  = (const float*)d_in[3];
    const float* W_ih  = (const float*)d_in[4];
    const float* W_hh  = (const float*)d_in[5];
    const float* b_ih  = (const float*)d_in[6];
    const float* b_hh  = (const float*)d_in[7];
    const float* out_w = (const float*)d_in[8];
    const float* out_b = (const float*)d_in[9];
    float* out = (float*)d_out;

    void* pv;
    cudaGetSymbolAddress(&pv, g_flat);     float* f_flat = (float*)pv;
    cudaGetSymbolAddress(&pv, g_h);        float* f_h    = (float*)pv;
    cudaGetSymbolAddress(&pv, g_Gc);       float* f_Gc   = (float*)pv;
    cudaGetSymbolAddress(&pv, g_WihE_hi);  __nv_bfloat16* w_ihe_h = (__nv_bfloat16*)pv;
    cudaGetSymbolAddress(&pv, g_WihE_lo);  __nv_bfloat16* w_ihe_l = (__nv_bfloat16*)pv;
    cudaGetSymbolAddress(&pv, g_Whh_hi);   __nv_bfloat16* w_hh_h  = (__nv_bfloat16*)pv;
    cudaGetSymbolAddress(&pv, g_Whh_lo);   __nv_bfloat16* w_hh_l  = (__nv_bfloat16*)pv;
    cudaGetSymbolAddress(&pv, g_Wout_hi);  __nv_bfloat16* w_o_h   = (__nv_bfloat16*)pv;

    cudaFuncSetAttribute(k_step, cudaFuncAttributeMaxDynamicSharedMemorySize, TCSMEM);

    // ---- one-time setup ----
    k_setup<<<256, 256>>>(enc);
    k_gemm<<<H_ / 64, 256>>>(f_flat, 2 * HENC, Wh_w, 2 * HENC, 0, 2 * HENC, Wh_b, f_h, H_);
    k_gemm<<<3 * H_ / 64, 256>>>(f_flat, 2 * HENC, W_ih, E_ + 2 * HENC, E_, 2 * HENC,
                                 b_ih, f_Gc, 3 * H_);
    k_split_h0<<<(B_ * H_) / 256, 256>>>();
    k_mk_gcT<<<(3 * H_ * B_) / 256, 256>>>();
    k_splitw<<<(3 * H_ * E_) / 256, 256>>>(W_ih, E_ + 2 * HENC, 0, E_,
                                           w_ihe_h, w_ihe_l, 3 * H_ * E_);
    k_splitw<<<(3 * H_ * H_) / 256, 256>>>(W_hh, H_, 0, H_,
                                           w_hh_h, w_hh_l, 3 * H_ * H_);
    k_splitw<<<(V_ * H_) / 256, 256>>>(out_w, H_, 0, H_,
                                       w_o_h, nullptr, V_ * H_);
    k_wnorms<<<V_ / 8, 256>>>(out_w);
    k_split_x<<<(B_ * E_) / 256, 256>>>(emb);   // SOS embeddings + norm reset

    // ---- decode loop: ONE fused kernel per step ----
    for (int t = 0; t < T_; t++)
        k_step<<<GRID_STEP, 256, TCSMEM>>>(b_hh, out_b, out_w, emb, out, t);

    if (out_size >= B_ * T_ + B_ * H_)
        k_writeh<<<(B_ * H_) / 256, 256>>>(out + B_ * T_);
}

// round 14
// speedup vs baseline: 1.2082x; 1.2082x over previous
#include <cuda_runtime.h>
#include <cuda_bf16.h>
#include <math.h>
#include <stdint.h>

static constexpr int B_   = 64;
static constexpr int HENC = 512;
static constexpr int E_   = 512;
static constexpr int H_   = 1024;
static constexpr int V_   = 32000;
static constexpr int T_   = 64;
static constexpr int SOS  = 1;
static constexpr int EOS  = 2;
static constexpr int CAND_CAP = 2048;

// ---------------- persistent device state ----------------
__device__ float g_flat[B_ * 2 * HENC];
__device__ float g_h[B_ * H_];
__device__ float g_Gc[B_ * 3 * H_];
__device__ float g_GcT[3 * H_ * B_];
__device__ float g_giT[3 * H_ * B_];
__device__ float g_giT2[3 * H_ * B_];        // split-K partial
__device__ float g_ghT[3 * H_ * B_];
__device__ float g_ghT2[3 * H_ * B_];        // split-K partial
__device__ int   g_inp[B_];
__device__ int   g_fin[B_];
__device__ float g_hnorm[2 * B_];            // per-batch {‖h_b‖², ‖h_b−h_hi‖²}
__device__ unsigned g_nmax[2];               // {max ‖Wh_row‖, max ‖Wl_row‖} float bits
__device__ unsigned g_amaxv[B_];             // per-batch max approx logit (ordered bits)
__device__ float g_applog[(size_t)B_ * V_];  // approx logits [batch][vocab]

// bf16 split weights / activations
__device__ __nv_bfloat16 g_WihE_hi[3 * H_ * E_];
__device__ __nv_bfloat16 g_WihE_lo[3 * H_ * E_];
__device__ __nv_bfloat16 g_Whh_hi[3 * H_ * H_];
__device__ __nv_bfloat16 g_Whh_lo[3 * H_ * H_];
__device__ __nv_bfloat16 g_Wout_hi[(size_t)V_ * H_];
__device__ __nv_bfloat16 g_x_hi[B_ * E_];
__device__ __nv_bfloat16 g_x_lo[B_ * E_];
__device__ __nv_bfloat16 g_h_hi[B_ * H_];
__device__ __nv_bfloat16 g_h_lo[B_ * H_];

// ---------------------------------------------------------------------------
__device__ __forceinline__ uint32_t smem_u32(const void* p) {
    uint32_t a;
    asm("{ .reg .u64 t; cvta.to.shared.u64 t, %1; cvt.u32.u64 %0, t; }"
        : "=r"(a) : "l"(p));
    return a;
}

__device__ __forceinline__ void cp16(uint32_t dst, const void* src) {
    asm volatile("cp.async.cg.shared.global [%0], [%1], 16;"
                 :: "r"(dst), "l"(src));
}
#define CP_COMMIT() asm volatile("cp.async.commit_group;")
#define CP_WAIT(n)  asm volatile("cp.async.wait_group %0;" :: "n"(n))

#define LDMX4(R0, R1, R2, R3, ADDR)                                           \
    asm volatile("ldmatrix.sync.aligned.m8n8.x4.shared.b16 {%0,%1,%2,%3}, [%4];" \
                 : "=r"(R0), "=r"(R1), "=r"(R2), "=r"(R3) : "r"(ADDR))

#define MMA16816(D, A, Bv)                                                    \
    asm volatile("mma.sync.aligned.m16n8k16.row.col.f32.bf16.bf16.f32 "       \
                 "{%0,%1,%2,%3},{%4,%5,%6,%7},{%8,%9},{%0,%1,%2,%3};"          \
                 : "+f"(D[0]), "+f"(D[1]), "+f"(D[2]), "+f"(D[3])              \
                 : "r"(A[0]), "r"(A[1]), "r"(A[2]), "r"(A[3]),                 \
                   "r"(Bv[0]), "r"(Bv[1]))

__device__ __forceinline__ unsigned ordbits(float v) {
    unsigned u = __float_as_uint(v);
    return (u & 0x80000000u) ? ~u : (u | 0x80000000u);
}
__device__ __forceinline__ float ordfloat(unsigned u) {
    return (u & 0x80000000u) ? __uint_as_float(u ^ 0x80000000u)
                             : __uint_as_float(~u);
}
__device__ __forceinline__ unsigned long long packkey(float v, int row) {
    return ((unsigned long long)ordbits(v) << 32) |
           (unsigned)(0xFFFFFFFFu - (unsigned)row);
}

// ---------------------------------------------------------------------------
// smem ring: per stage [A_hi(10240) | A_lo(10240 if S2) | B_hi(5120) | B_lo]
// ---------------------------------------------------------------------------
static constexpr int SROW = 40;
template <int SPLITS>
__device__ __forceinline__ uint32_t abuf_off(int st, int sp) {
    return (uint32_t)(st * (SPLITS * 15360) + sp * 10240);
}
template <int SPLITS>
__device__ __forceinline__ uint32_t bbuf_off(int st, int sp) {
    return (uint32_t)(st * (SPLITS * 15360) + SPLITS * 10240 + sp * 5120);
}
static constexpr int TCSMEM_GATES  = 61440;   // SPLITS=2, 2 stages
static constexpr int TCSMEM_LOGITS = 46080;   // SPLITS=1, 3 stages

// ---------------------------------------------------------------------------
// Core GEMM: D = A[128 rows, Kext] @ B[64, Kext]^T, row stride ld (>= Kext).
// SPLITS=2: 3-product bf16 split;  SPLITS=1: hi-only.  STAGES-deep cp.async.
// MODE 0: D[r*64+c] = acc + bias[r] + addT[r*64+c]
// MODE 2: g_applog[c*V + r] = acc + bias[r]; fused per-column max -> s_cmax
// ---------------------------------------------------------------------------
template <int MODE, int SPLITS, int STAGES>
__device__ __forceinline__ void mma_core(
    const __nv_bfloat16* __restrict__ Ah, const __nv_bfloat16* __restrict__ Al,
    const __nv_bfloat16* __restrict__ Bh, const __nv_bfloat16* __restrict__ Bl,
    int ld, int Kext, const float* __restrict__ bias,
    const float* __restrict__ addT, float* __restrict__ D, int m0,
    unsigned* s_cmax)
{
    extern __shared__ __align__(16) char smem[];
    const uint32_t sb = smem_u32(smem);
    const int tid = threadIdx.x, lane = tid & 31, warp = tid >> 5;
    const int mw = warp * 16;

    float acc[8][4];
#pragma unroll
    for (int f = 0; f < 8; f++)
#pragma unroll
        for (int j = 0; j < 4; j++) acc[f][j] = 0.f;

    const int a_row  = mw + ((lane >> 3) & 1) * 8 + (lane & 7);
    const int a_koff = (lane >> 4) * 8;
    const int b_row  = (lane >> 4) * 8 + (lane & 7);
    const int b_koff = ((lane >> 3) & 1) * 8;

    const int nch = Kext >> 5;

    auto stage = [&](int kc, int st) {
        const int kb = kc << 5;
#pragma unroll
        for (int i = 0; i < 2; i++) {
            int id = tid + (i << 8);
            int r = id >> 2, c = id & 3;
            uint32_t so = (uint32_t)(r * 80 + c * 16);
            const size_t go = (size_t)(m0 + r) * ld + kb + c * 8;
            cp16(sb + abuf_off<SPLITS>(st, 0) + so, Ah + go);
            if (SPLITS == 2) cp16(sb + abuf_off<SPLITS>(st, 1) + so, Al + go);
        }
        {
            int r = tid >> 2, c = tid & 3;
            uint32_t so = (uint32_t)(r * 80 + c * 16);
            const size_t go = (size_t)r * ld + kb + c * 8;
            cp16(sb + bbuf_off<SPLITS>(st, 0) + so, Bh + go);
            if (SPLITS == 2) cp16(sb + bbuf_off<SPLITS>(st, 1) + so, Bl + go);
        }
    };

    // prologue: STAGES-1 chunks in flight
#pragma unroll
    for (int s = 0; s < STAGES - 1; s++) {
        if (s < nch) { stage(s, s); CP_COMMIT(); }
    }

    for (int kc = 0; kc < nch; kc++) {
        const int cur = kc % STAGES;
        const int nxt = kc + STAGES - 1;
        if (nxt < nch) {
            stage(nxt, nxt % STAGES);
            CP_COMMIT();
            if (STAGES == 3) CP_WAIT(2); else CP_WAIT(1);
        } else {
            const int rem = nch - 1 - kc;
            if (rem >= 1) CP_WAIT(1); else CP_WAIT(0);
        }
        __syncthreads();

#pragma unroll
        for (int ks = 0; ks < 2; ks++) {
            const int kk = ks * 16;
            uint32_t ah[4], al[4];
            {
                uint32_t ad = sb + abuf_off<SPLITS>(cur, 0) +
                              (uint32_t)((a_row * SROW + kk + a_koff) * 2);
                LDMX4(ah[0], ah[1], ah[2], ah[3], ad);
                if (SPLITS == 2) {
                    ad = sb + abuf_off<SPLITS>(cur, 1) +
                         (uint32_t)((a_row * SROW + kk + a_koff) * 2);
                    LDMX4(al[0], al[1], al[2], al[3], ad);
                }
            }
            uint32_t bh[8][2], bl[8][2];
#pragma unroll
            for (int p = 0; p < 4; p++) {
                uint32_t ad = sb + bbuf_off<SPLITS>(cur, 0) +
                              (uint32_t)(((p * 16 + b_row) * SROW + kk + b_koff) * 2);
                LDMX4(bh[2 * p][0], bh[2 * p][1], bh[2 * p + 1][0], bh[2 * p + 1][1], ad);
                if (SPLITS == 2) {
                    ad = sb + bbuf_off<SPLITS>(cur, 1) +
                         (uint32_t)(((p * 16 + b_row) * SROW + kk + b_koff) * 2);
                    LDMX4(bl[2 * p][0], bl[2 * p][1], bl[2 * p + 1][0], bl[2 * p + 1][1], ad);
                }
            }
#pragma unroll
            for (int f = 0; f < 8; f++) {
                MMA16816(acc[f], ah, bh[f]);
                if (SPLITS == 2) {
                    MMA16816(acc[f], ah, bl[f]);
                    MMA16816(acc[f], al, bh[f]);
                }
            }
        }
        __syncthreads();
    }

    const int g  = lane >> 2;
    const int tq = lane & 3;
    const int r0 = m0 + mw + g;
    const int r1 = r0 + 8;
    const float b0v = bias ? bias[r0] : 0.f;
    const float b1v = bias ? bias[r1] : 0.f;

    if (MODE == 0) {
#pragma unroll
        for (int f = 0; f < 8; f++) {
#pragma unroll
            for (int j = 0; j < 2; j++) {
                const int c = f * 8 + tq * 2 + j;
                float v0 = acc[f][j]     + b0v;
                float v1 = acc[f][2 + j] + b1v;
                if (addT) {
                    v0 += addT[(size_t)r0 * 64 + c];
                    v1 += addT[(size_t)r1 * 64 + c];
                }
                D[(size_t)r0 * 64 + c] = v0;
                D[(size_t)r1 * 64 + c] = v1;
            }
        }
    } else {
        unsigned cm[16];
#pragma unroll
        for (int q = 0; q < 16; q++) cm[q] = 0u;
#pragma unroll
        for (int f = 0; f < 8; f++) {
#pragma unroll
            for (int j = 0; j < 2; j++) {
                const int c = f * 8 + tq * 2 + j;
                float v0 = acc[f][j]     + b0v;
                float v1 = acc[f][2 + j] + b1v;
                g_applog[(size_t)c * V_ + r0] = v0;
                g_applog[(size_t)c * V_ + r1] = v1;
                unsigned u = ordbits(v0), w = ordbits(v1);
                cm[f * 2 + j] = (u > w) ? u : w;
            }
        }
#pragma unroll
        for (int s = 4; s <= 16; s <<= 1)
#pragma unroll
            for (int q = 0; q < 16; q++) {
                unsigned o = __shfl_xor_sync(0xffffffffu, cm[q], s);
                if (o > cm[q]) cm[q] = o;
            }
        if (lane < 4) {
#pragma unroll
            for (int f = 0; f < 8; f++)
#pragma unroll
                for (int j = 0; j < 2; j++)
                    atomicMax(&s_cmax[f * 8 + lane * 2 + j], cm[f * 2 + j]);
        }
    }
}

// gates with 2-way split-K: grid (24, 4)
// y=0: gi K[0:256) (+GcT)   y=1: gi K[256:512) -> g_giT2
// y=2: gh K[0:512) (+b_hh)  y=3: gh K[512:1024) -> g_ghT2
__global__ void __launch_bounds__(256) k_tc_gates(const float* __restrict__ b_hh) {
    const int m0 = blockIdx.x * 128;
    switch (blockIdx.y) {
    case 0:
        mma_core<0, 2, 2>(g_WihE_hi, g_WihE_lo, g_x_hi, g_x_lo,
                          E_, E_ / 2, nullptr, g_GcT, g_giT, m0, nullptr);
        break;
    case 1:
        mma_core<0, 2, 2>(g_WihE_hi + E_ / 2, g_WihE_lo + E_ / 2,
                          g_x_hi + E_ / 2, g_x_lo + E_ / 2,
                          E_, E_ / 2, nullptr, nullptr, g_giT2, m0, nullptr);
        break;
    case 2:
        mma_core<0, 2, 2>(g_Whh_hi, g_Whh_lo, g_h_hi, g_h_lo,
                          H_, H_ / 2, b_hh, nullptr, g_ghT, m0, nullptr);
        break;
    default:
        mma_core<0, 2, 2>(g_Whh_hi + H_ / 2, g_Whh_lo + H_ / 2,
                          g_h_hi + H_ / 2, g_h_lo + H_ / 2,
                          H_, H_ / 2, nullptr, nullptr, g_ghT2, m0, nullptr);
    }
}

// logits: 250 CTAs (~2/SM), 3-stage pipeline, fused per-batch col-max
__global__ void __launch_bounds__(256) k_tc_logits(const float* __restrict__ out_b) {
    __shared__ unsigned s_cmax[B_];
    if (threadIdx.x < B_) s_cmax[threadIdx.x] = 0u;
    mma_core<2, 1, 3>(g_Wout_hi, nullptr, g_h_hi, nullptr,
                      H_, H_, out_b, nullptr, nullptr, blockIdx.x * 128, s_cmax);
    __syncthreads();
    if (threadIdx.x < B_) atomicMax(&g_amaxv[threadIdx.x], s_cmax[threadIdx.x]);
}

// ---------------------------------------------------------------------------
__global__ void k_setup(const float* __restrict__ enc) {
    int idx = blockIdx.x * blockDim.x + threadIdx.x;
    if (idx < B_ * 2 * HENC) {
        int b = idx / (2 * HENC);
        int k = idx % (2 * HENC);
        float v = (k < HENC) ? enc[b * HENC + k]
                             : enc[B_ * HENC + b * HENC + (k - HENC)];
        g_flat[idx] = v;
    }
    if (idx < B_) { g_inp[idx] = SOS; g_fin[idx] = 0; g_amaxv[idx] = 0u; }
    if (idx < 2)  { g_nmax[idx] = 0u; }
}

__global__ void __launch_bounds__(256) k_gemm(
    const float* __restrict__ A, int lda,
    const float* __restrict__ W, int ldw, int woff, int K,
    const float* __restrict__ bias, float* __restrict__ C, int ldc)
{
    __shared__ float As[32][68];
    __shared__ float Ws[32][68];
    const int tid = threadIdx.x;
    const int tx = tid & 15, ty = tid >> 4;
    const int n0 = blockIdx.x * 64;
    float acc[4][4] = {};

    for (int k0 = 0; k0 < K; k0 += 32) {
#pragma unroll
        for (int it = 0; it < 2; it++) {
            int idx = tid + it * 256;
            int row = idx >> 3;
            int kq  = (idx & 7) << 2;
            float4 v = *(const float4*)(A + (size_t)row * lda + k0 + kq);
            As[kq][row] = v.x; As[kq + 1][row] = v.y;
            As[kq + 2][row] = v.z; As[kq + 3][row] = v.w;
            float4 u = *(const float4*)(W + (size_t)(n0 + row) * ldw + woff + k0 + kq);
            Ws[kq][row] = u.x; Ws[kq + 1][row] = u.y;
            Ws[kq + 2][row] = u.z; Ws[kq + 3][row] = u.w;
        }
        __syncthreads();
#pragma unroll
        for (int k = 0; k < 32; k++) {
            float4 a = *(const float4*)&As[k][ty << 2];
            float4 w = *(const float4*)&Ws[k][tx << 2];
            acc[0][0] += a.x * w.x; acc[0][1] += a.x * w.y; acc[0][2] += a.x * w.z; acc[0][3] += a.x * w.w;
            acc[1][0] += a.y * w.x; acc[1][1] += a.y * w.y; acc[1][2] += a.y * w.z; acc[1][3] += a.y * w.w;
            acc[2][0] += a.z * w.x; acc[2][1] += a.z * w.y; acc[2][2] += a.z * w.z; acc[2][3] += a.z * w.w;
            acc[3][0] += a.w * w.x; acc[3][1] += a.w * w.y; acc[3][2] += a.w * w.z; acc[3][3] += a.w * w.w;
        }
        __syncthreads();
    }
#pragma unroll
    for (int i = 0; i < 4; i++) {
        int row = (ty << 2) + i;
#pragma unroll
        for (int j = 0; j < 4; j++) {
            int col = n0 + (tx << 2) + j;
            float v = acc[i][j];
            if (bias) v += bias[col];
            C[(size_t)row * ldc + col] = v;
        }
    }
}

__global__ void k_splitw(const float* __restrict__ src, int ld, int coloff, int cols,
                         __nv_bfloat16* __restrict__ hi, __nv_bfloat16* __restrict__ lo,
                         int n)
{
    int idx = blockIdx.x * blockDim.x + threadIdx.x;
    if (idx >= n) return;
    int r = idx / cols, c = idx % cols;
    float v = src[(size_t)r * ld + coloff + c];
    __nv_bfloat16 h = __float2bfloat16(v);
    hi[idx] = h;
    if (lo) lo[idx] = __float2bfloat16(v - __bfloat162float(h));
}

__global__ void k_split_h0() {
    int idx = blockIdx.x * blockDim.x + threadIdx.x;
    if (idx >= B_ * H_) return;
    float v = g_h[idx];
    __nv_bfloat16 h = __float2bfloat16(v);
    g_h_hi[idx] = h;
    g_h_lo[idx] = __float2bfloat16(v - __bfloat162float(h));
}

__global__ void k_mk_gcT() {
    int idx = blockIdx.x * blockDim.x + threadIdx.x;
    if (idx >= 3 * H_ * B_) return;
    int r = idx >> 6, c = idx & 63;
    g_GcT[idx] = g_Gc[(size_t)c * (3 * H_) + r];
}

__global__ void k_wnorms(const float* __restrict__ out_w) {
    int r = blockIdx.x * 8 + (threadIdx.x >> 5);
    int lane = threadIdx.x & 31;
    if (r >= V_) return;
    float sh = 0.f, sl = 0.f;
    for (int k = lane; k < H_; k += 32) {
        float w  = out_w[(size_t)r * H_ + k];
        float wh = __bfloat162float(g_Wout_hi[(size_t)r * H_ + k]);
        float wl = w - wh;
        sh += wh * wh;
        sl += wl * wl;
    }
#pragma unroll
    for (int s = 16; s > 0; s >>= 1) {
        sh += __shfl_xor_sync(0xffffffffu, sh, s);
        sl += __shfl_xor_sync(0xffffffffu, sl, s);
    }
    if (lane == 0) {
        atomicMax(&g_nmax[0], __float_as_uint(sqrtf(sh)));
        atomicMax(&g_nmax[1], __float_as_uint(sqrtf(sl)));
    }
}

// initial x split (SOS) + hnorm reset — pre-loop only
__global__ void k_split_x(const float* __restrict__ emb) {
    int idx = blockIdx.x * blockDim.x + threadIdx.x;
    if (idx < 2 * B_) g_hnorm[idx] = 0.f;
    if (idx >= B_ * E_) return;
    int b = idx >> 9;
    int k = idx & (E_ - 1);
    float v = emb[(size_t)g_inp[b] * E_ + k];
    __nv_bfloat16 h = __float2bfloat16(v);
    g_x_hi[idx] = h;
    g_x_lo[idx] = __float2bfloat16(v - __bfloat162float(h));
}

// GRU gates (summing split-K partials) + h split + per-batch norms
__global__ void __launch_bounds__(256) k_gates2() {
    __shared__ float sb1[B_], sb2[B_];
    int tid = threadIdx.x;
    if (tid < B_) { sb1[tid] = 0.f; sb2[tid] = 0.f; }
    __syncthreads();

    int idx = blockIdx.x * 256 + tid;
    int b = idx & (B_ - 1);
    int i = idx >> 6;
    float ir  = g_giT[(size_t)i * 64 + b]            + g_giT2[(size_t)i * 64 + b];
    float iz  = g_giT[(size_t)(H_ + i) * 64 + b]     + g_giT2[(size_t)(H_ + i) * 64 + b];
    float in_ = g_giT[(size_t)(2 * H_ + i) * 64 + b] + g_giT2[(size_t)(2 * H_ + i) * 64 + b];
    float hr  = g_ghT[(size_t)i * 64 + b]            + g_ghT2[(size_t)i * 64 + b];
    float hz  = g_ghT[(size_t)(H_ + i) * 64 + b]     + g_ghT2[(size_t)(H_ + i) * 64 + b];
    float hn  = g_ghT[(size_t)(2 * H_ + i) * 64 + b] + g_ghT2[(size_t)(2 * H_ + i) * 64 + b];
    float r = 1.f / (1.f + expf(-(ir + hr)));
    float z = 1.f / (1.f + expf(-(iz + hz)));
    float n = tanhf(in_ + r * hn);
    size_t hidx = (size_t)b * H_ + i;
    float h = g_h[hidx];
    float hnew = (1.f - z) * n + z * h;
    g_h[hidx] = hnew;
    __nv_bfloat16 hh = __float2bfloat16(hnew);
    g_h_hi[hidx] = hh;
    float res = hnew - __bfloat162float(hh);
    g_h_lo[hidx] = __float2bfloat16(res);

    atomicAdd(&sb1[b], hnew * hnew);
    atomicAdd(&sb2[b], res * res);
    __syncthreads();
    if (tid < B_) {
        atomicAdd(&g_hnorm[tid],      sb1[tid]);
        atomicAdd(&g_hnorm[B_ + tid], sb2[tid]);
    }
}

// ---------------------------------------------------------------------------
// Rescore: per-batch bound (using fused g_amaxv), exact fp32 rescore,
// full-scan fallback, fused next-x embed split + per-step resets.
// ---------------------------------------------------------------------------
__global__ void __launch_bounds__(256) k_rescore(
    const float* __restrict__ out_w, const float* __restrict__ out_b,
    const float* __restrict__ emb, float* __restrict__ out_tok, int t)
{
    __shared__ float sh_h[H_];
    __shared__ int cand[CAND_CAP];
    __shared__ int cnt;
    __shared__ unsigned long long bestkey;
    __shared__ int s_tok;

    const int b = blockIdx.x;
    const int tid = threadIdx.x, lane = tid & 31, warp = tid >> 5;
    const float* ap = g_applog + (size_t)b * V_;

    for (int i = tid; i < H_; i += 256) sh_h[i] = g_h[(size_t)b * H_ + i];
    if (tid == 0) { cnt = 0; bestkey = 0ULL; }
    __syncthreads();

    const float A   = ordfloat(g_amaxv[b]);
    const float nh  = sqrtf(g_hnorm[b]);
    const float nhl = sqrtf(g_hnorm[B_ + b]);
    const float nwh = __uint_as_float(g_nmax[0]);
    const float nwl = __uint_as_float(g_nmax[1]);
    const float eps = 2.f * (nwl * nh + nwh * nhl) + 0.1f;
    const float thresh = A - eps;

    for (int r = tid; r < V_; r += 256) {
        if (ap[r] >= thresh) {
            int i = atomicAdd(&cnt, 1);
            if (i < CAND_CAP) cand[i] = r;
        }
    }
    __syncthreads();

    if (cnt <= CAND_CAP) {
        const int nc = cnt;
        for (int ci = warp; ci < nc; ci += 8) {
            const int r = cand[ci];
            float s = 0.f;
            for (int k = lane; k < H_; k += 32)
                s += out_w[(size_t)r * H_ + k] * sh_h[k];
#pragma unroll
            for (int sft = 16; sft > 0; sft >>= 1)
                s += __shfl_xor_sync(0xffffffffu, s, sft);
            if (lane == 0)
                atomicMax(&bestkey, packkey(s + out_b[r], r));
        }
    } else {
        for (int r = warp; r < V_; r += 8) {
            float s = 0.f;
            for (int k = lane; k < H_; k += 32)
                s += out_w[(size_t)r * H_ + k] * sh_h[k];
#pragma unroll
            for (int sft = 16; sft > 0; sft >>= 1)
                s += __shfl_xor_sync(0xffffffffu, s, sft);
            if (lane == 0)
                atomicMax(&bestkey, packkey(s + out_b[r], r));
        }
    }
    __syncthreads();

    if (tid == 0) {
        int tok = (int)(0xFFFFFFFFu - (unsigned)(bestkey & 0xFFFFFFFFull));
        out_tok[b * T_ + t] = (float)tok;
        int fin = g_fin[b] | (tok == EOS);
        g_fin[b] = fin;
        int ninp = fin ? EOS : tok;
        g_inp[b] = ninp;
        s_tok = ninp;
        g_amaxv[b] = 0u;
    }
    __syncthreads();

    const int ninp = s_tok;
    for (int k = tid; k < E_; k += 256) {
        float v = emb[(size_t)ninp * E_ + k];
        __nv_bfloat16 h = __float2bfloat16(v);
        g_x_hi[b * E_ + k] = h;
        g_x_lo[b * E_ + k] = __float2bfloat16(v - __bfloat162float(h));
    }
    if (tid < 2) g_hnorm[tid * B_ + b] = 0.f;
}

__global__ void k_writeh(float* __restrict__ out_h) {
    int idx = blockIdx.x * blockDim.x + threadIdx.x;
    if (idx < B_ * H_) out_h[idx] = g_h[idx];
}

// ---------------------------------------------------------------------------
extern "C" void kernel_launch(void* const* d_in, const int* in_sizes, int n_in,
                              void* d_out, int out_size) {
    const float* enc   = (const float*)d_in[0];
    const float* emb   = (const float*)d_in[1];
    const float* Wh_w  = (const float*)d_in[2];
    const float* Wh_b  = (const float*)d_in[3];
    const float* W_ih  = (const float*)d_in[4];
    const float* W_hh  = (const float*)d_in[5];
    const float* b_ih  = (const float*)d_in[6];
    const float* b_hh  = (const float*)d_in[7];
    const float* out_w = (const float*)d_in[8];
    const float* out_b = (const float*)d_in[9];
    float* out = (float*)d_out;

    void* pv;
    cudaGetSymbolAddress(&pv, g_flat);     float* f_flat = (float*)pv;
    cudaGetSymbolAddress(&pv, g_h);        float* f_h    = (float*)pv;
    cudaGetSymbolAddress(&pv, g_Gc);       float* f_Gc   = (float*)pv;
    cudaGetSymbolAddress(&pv, g_WihE_hi);  __nv_bfloat16* w_ihe_h = (__nv_bfloat16*)pv;
    cudaGetSymbolAddress(&pv, g_WihE_lo);  __nv_bfloat16* w_ihe_l = (__nv_bfloat16*)pv;
    cudaGetSymbolAddress(&pv, g_Whh_hi);   __nv_bfloat16* w_hh_h  = (__nv_bfloat16*)pv;
    cudaGetSymbolAddress(&pv, g_Whh_lo);   __nv_bfloat16* w_hh_l  = (__nv_bfloat16*)pv;
    cudaGetSymbolAddress(&pv, g_Wout_hi);  __nv_bfloat16* w_o_h   = (__nv_bfloat16*)pv;

    cudaFuncSetAttribute(k_tc_gates,  cudaFuncAttributeMaxDynamicSharedMemorySize, TCSMEM_GATES);
    cudaFuncSetAttribute(k_tc_logits, cudaFuncAttributeMaxDynamicSharedMemorySize, TCSMEM_LOGITS);

    // ---- one-time setup ----
    k_setup<<<256, 256>>>(enc);
    k_gemm<<<H_ / 64, 256>>>(f_flat, 2 * HENC, Wh_w, 2 * HENC, 0, 2 * HENC, Wh_b, f_h, H_);
    k_gemm<<<3 * H_ / 64, 256>>>(f_flat, 2 * HENC, W_ih, E_ + 2 * HENC, E_, 2 * HENC,
                                 b_ih, f_Gc, 3 * H_);
    k_split_h0<<<(B_ * H_) / 256, 256>>>();
    k_mk_gcT<<<(3 * H_ * B_) / 256, 256>>>();
    k_splitw<<<(3 * H_ * E_) / 256, 256>>>(W_ih, E_ + 2 * HENC, 0, E_,
                                           w_ihe_h, w_ihe_l, 3 * H_ * E_);
    k_splitw<<<(3 * H_ * H_) / 256, 256>>>(W_hh, H_, 0, H_,
                                           w_hh_h, w_hh_l, 3 * H_ * H_);
    k_splitw<<<(V_ * H_) / 256, 256>>>(out_w, H_, 0, H_,
                                       w_o_h, nullptr, V_ * H_);
    k_wnorms<<<V_ / 8, 256>>>(out_w);
    k_split_x<<<(B_ * E_) / 256, 256>>>(emb);

    // ---- decode loop (4 kernels/step) ----
    dim3 ggates(3 * H_ / 128, 4);
    for (int t = 0; t < T_; t++) {
        k_tc_gates<<<ggates, 256, TCSMEM_GATES>>>(b_hh);
        k_gates2<<<(B_ * H_) / 256, 256>>>();
        k_tc_logits<<<V_ / 128, 256, TCSMEM_LOGITS>>>(out_b);
        k_rescore<<<B_, 256>>>(out_w, out_b, emb, out, t);
    }

    if (out_size >= B_ * T_ + B_ * H_)
        k_writeh<<<(B_ * H_) / 256, 256>>>(out + B_ * T_);
}

// round 15
// speedup vs baseline: 1.3015x; 1.0772x over previous
#include <cuda_runtime.h>
#include <cuda_bf16.h>
#include <math.h>
#include <stdint.h>

static constexpr int B_   = 64;
static constexpr int HENC = 512;
static constexpr int E_   = 512;
static constexpr int H_   = 1024;
static constexpr int V_   = 32000;
static constexpr int T_   = 64;
static constexpr int SOS  = 1;
static constexpr int EOS  = 2;
static constexpr int CAND_CAP = 2048;

// ---------------- persistent device state ----------------
__device__ float g_flat[B_ * 2 * HENC];
__device__ float g_h[B_ * H_];
__device__ float g_Gc[B_ * 3 * H_];
__device__ float g_GcT[3 * H_ * B_];
__device__ float g_giT[3 * H_ * B_];
__device__ float g_giT2[3 * H_ * B_];
__device__ float g_ghT[3 * H_ * B_];
__device__ float g_ghT2[3 * H_ * B_];
__device__ float g_ghT3[3 * H_ * B_];
__device__ float g_ghT4[3 * H_ * B_];
__device__ int   g_inp[B_];
__device__ int   g_fin[B_];
__device__ float g_hnorm[2 * B_];            // per-batch {‖h_b‖², ‖h_b−h_hi‖²}
__device__ unsigned g_nmax[2];               // {max ‖Wh_row‖, max ‖Wl_row‖} float bits
__device__ unsigned g_amaxv[B_];             // per-batch max approx logit (ordered bits)
__device__ float g_applog[(size_t)B_ * V_];  // approx logits [batch][vocab]

// bf16 split weights / activations
__device__ __nv_bfloat16 g_WihE_hi[3 * H_ * E_];
__device__ __nv_bfloat16 g_WihE_lo[3 * H_ * E_];
__device__ __nv_bfloat16 g_Whh_hi[3 * H_ * H_];
__device__ __nv_bfloat16 g_Whh_lo[3 * H_ * H_];
__device__ __nv_bfloat16 g_Wout_hi[(size_t)V_ * H_];
__device__ __nv_bfloat16 g_x_hi[B_ * E_];
__device__ __nv_bfloat16 g_x_lo[B_ * E_];
__device__ __nv_bfloat16 g_h_hi[B_ * H_];
__device__ __nv_bfloat16 g_h_lo[B_ * H_];

// ---------------------------------------------------------------------------
__device__ __forceinline__ uint32_t smem_u32(const void* p) {
    uint32_t a;
    asm("{ .reg .u64 t; cvta.to.shared.u64 t, %1; cvt.u32.u64 %0, t; }"
        : "=r"(a) : "l"(p));
    return a;
}

__device__ __forceinline__ void cp16(uint32_t dst, const void* src) {
    asm volatile("cp.async.cg.shared.global [%0], [%1], 16;"
                 :: "r"(dst), "l"(src));
}
#define CP_COMMIT() asm volatile("cp.async.commit_group;")
#define CP_WAIT(n)  asm volatile("cp.async.wait_group %0;" :: "n"(n))

#define LDMX4(R0, R1, R2, R3, ADDR)                                           \
    asm volatile("ldmatrix.sync.aligned.m8n8.x4.shared.b16 {%0,%1,%2,%3}, [%4];" \
                 : "=r"(R0), "=r"(R1), "=r"(R2), "=r"(R3) : "r"(ADDR))

#define MMA16816(D, A, Bv)                                                    \
    asm volatile("mma.sync.aligned.m16n8k16.row.col.f32.bf16.bf16.f32 "       \
                 "{%0,%1,%2,%3},{%4,%5,%6,%7},{%8,%9},{%0,%1,%2,%3};"          \
                 : "+f"(D[0]), "+f"(D[1]), "+f"(D[2]), "+f"(D[3])              \
                 : "r"(A[0]), "r"(A[1]), "r"(A[2]), "r"(A[3]),                 \
                   "r"(Bv[0]), "r"(Bv[1]))

__device__ __forceinline__ unsigned ordbits(float v) {
    unsigned u = __float_as_uint(v);
    return (u & 0x80000000u) ? ~u : (u | 0x80000000u);
}
__device__ __forceinline__ float ordfloat(unsigned u) {
    return (u & 0x80000000u) ? __uint_as_float(u ^ 0x80000000u)
                             : __uint_as_float(~u);
}
__device__ __forceinline__ unsigned long long packkey(float v, int row) {
    return ((unsigned long long)ordbits(v) << 32) |
           (unsigned)(0xFFFFFFFFu - (unsigned)row);
}

// ---------------------------------------------------------------------------
// smem ring: per stage [A_hi(10240) | A_lo(10240 if S2) | B_hi(5120) | B_lo]
// ---------------------------------------------------------------------------
static constexpr int SROW = 40;
template <int SPLITS>
__device__ __forceinline__ uint32_t abuf_off(int st, int sp) {
    return (uint32_t)(st * (SPLITS * 15360) + sp * 10240);
}
template <int SPLITS>
__device__ __forceinline__ uint32_t bbuf_off(int st, int sp) {
    return (uint32_t)(st * (SPLITS * 15360) + SPLITS * 10240 + sp * 5120);
}
static constexpr int TCSMEM_GATES  = 61440;   // SPLITS=2, 2 stages
static constexpr int TCSMEM_LOGITS = 61440;   // SPLITS=1, 4 stages

// ---------------------------------------------------------------------------
// Core GEMM: D = A[128 rows, Kext] @ B[64, Kext]^T, row stride ld (>= Kext).
// SPLITS=2: 3-product bf16 split;  SPLITS=1: hi-only.  STAGES-deep cp.async.
// MODE 0: D[r*64+c] = acc + bias[r] + addT[r*64+c]
// MODE 2: g_applog[c*V + r] = acc + bias[r]; fused per-column max -> s_cmax
// ---------------------------------------------------------------------------
template <int MODE, int SPLITS, int STAGES>
__device__ __forceinline__ void mma_core(
    const __nv_bfloat16* __restrict__ Ah, const __nv_bfloat16* __restrict__ Al,
    const __nv_bfloat16* __restrict__ Bh, const __nv_bfloat16* __restrict__ Bl,
    int ld, int Kext, const float* __restrict__ bias,
    const float* __restrict__ addT, float* __restrict__ D, int m0,
    unsigned* s_cmax)
{
    extern __shared__ __align__(16) char smem[];
    const uint32_t sb = smem_u32(smem);
    const int tid = threadIdx.x, lane = tid & 31, warp = tid >> 5;
    const int mw = warp * 16;

    float acc[8][4];
#pragma unroll
    for (int f = 0; f < 8; f++)
#pragma unroll
        for (int j = 0; j < 4; j++) acc[f][j] = 0.f;

    const int a_row  = mw + ((lane >> 3) & 1) * 8 + (lane & 7);
    const int a_koff = (lane >> 4) * 8;
    const int b_row  = (lane >> 4) * 8 + (lane & 7);
    const int b_koff = ((lane >> 3) & 1) * 8;

    const int nch = Kext >> 5;

    auto stage = [&](int kc, int st) {
        const int kb = kc << 5;
#pragma unroll
        for (int i = 0; i < 2; i++) {
            int id = tid + (i << 8);
            int r = id >> 2, c = id & 3;
            uint32_t so = (uint32_t)(r * 80 + c * 16);
            const size_t go = (size_t)(m0 + r) * ld + kb + c * 8;
            cp16(sb + abuf_off<SPLITS>(st, 0) + so, Ah + go);
            if (SPLITS == 2) cp16(sb + abuf_off<SPLITS>(st, 1) + so, Al + go);
        }
        {
            int r = tid >> 2, c = tid & 3;
            uint32_t so = (uint32_t)(r * 80 + c * 16);
            const size_t go = (size_t)r * ld + kb + c * 8;
            cp16(sb + bbuf_off<SPLITS>(st, 0) + so, Bh + go);
            if (SPLITS == 2) cp16(sb + bbuf_off<SPLITS>(st, 1) + so, Bl + go);
        }
    };

    // prologue: STAGES-1 chunks in flight
#pragma unroll
    for (int s = 0; s < STAGES - 1; s++) {
        if (s < nch) { stage(s, s); CP_COMMIT(); }
    }

    for (int kc = 0; kc < nch; kc++) {
        const int cur = kc % STAGES;
        const int nxt = kc + STAGES - 1;
        if (nxt < nch) {
            stage(nxt, nxt % STAGES);
            CP_COMMIT();
            if (STAGES == 4) CP_WAIT(3);
            else if (STAGES == 3) CP_WAIT(2);
            else CP_WAIT(1);
        } else {
            // rem chunks after kc are still in flight; need chunk kc complete
            const int rem = nch - 1 - kc;
            if (rem >= 3)      CP_WAIT(3);
            else if (rem == 2) CP_WAIT(2);
            else if (rem == 1) CP_WAIT(1);
            else               CP_WAIT(0);
        }
        __syncthreads();

#pragma unroll
        for (int ks = 0; ks < 2; ks++) {
            const int kk = ks * 16;
            uint32_t ah[4], al[4];
            {
                uint32_t ad = sb + abuf_off<SPLITS>(cur, 0) +
                              (uint32_t)((a_row * SROW + kk + a_koff) * 2);
                LDMX4(ah[0], ah[1], ah[2], ah[3], ad);
                if (SPLITS == 2) {
                    ad = sb + abuf_off<SPLITS>(cur, 1) +
                         (uint32_t)((a_row * SROW + kk + a_koff) * 2);
                    LDMX4(al[0], al[1], al[2], al[3], ad);
                }
            }
            uint32_t bh[8][2], bl[8][2];
#pragma unroll
            for (int p = 0; p < 4; p++) {
                uint32_t ad = sb + bbuf_off<SPLITS>(cur, 0) +
                              (uint32_t)(((p * 16 + b_row) * SROW + kk + b_koff) * 2);
                LDMX4(bh[2 * p][0], bh[2 * p][1], bh[2 * p + 1][0], bh[2 * p + 1][1], ad);
                if (SPLITS == 2) {
                    ad = sb + bbuf_off<SPLITS>(cur, 1) +
                         (uint32_t)(((p * 16 + b_row) * SROW + kk + b_koff) * 2);
                    LDMX4(bl[2 * p][0], bl[2 * p][1], bl[2 * p + 1][0], bl[2 * p + 1][1], ad);
                }
            }
#pragma unroll
            for (int f = 0; f < 8; f++) {
                MMA16816(acc[f], ah, bh[f]);
                if (SPLITS == 2) {
                    MMA16816(acc[f], ah, bl[f]);
                    MMA16816(acc[f], al, bh[f]);
                }
            }
        }
        __syncthreads();
    }

    const int g  = lane >> 2;
    const int tq = lane & 3;
    const int r0 = m0 + mw + g;
    const int r1 = r0 + 8;
    const float b0v = bias ? bias[r0] : 0.f;
    const float b1v = bias ? bias[r1] : 0.f;

    if (MODE == 0) {
#pragma unroll
        for (int f = 0; f < 8; f++) {
#pragma unroll
            for (int j = 0; j < 2; j++) {
                const int c = f * 8 + tq * 2 + j;
                float v0 = acc[f][j]     + b0v;
                float v1 = acc[f][2 + j] + b1v;
                if (addT) {
                    v0 += addT[(size_t)r0 * 64 + c];
                    v1 += addT[(size_t)r1 * 64 + c];
                }
                D[(size_t)r0 * 64 + c] = v0;
                D[(size_t)r1 * 64 + c] = v1;
            }
        }
    } else {
        unsigned cm[16];
#pragma unroll
        for (int q = 0; q < 16; q++) cm[q] = 0u;
#pragma unroll
        for (int f = 0; f < 8; f++) {
#pragma unroll
            for (int j = 0; j < 2; j++) {
                const int c = f * 8 + tq * 2 + j;
                float v0 = acc[f][j]     + b0v;
                float v1 = acc[f][2 + j] + b1v;
                g_applog[(size_t)c * V_ + r0] = v0;
                g_applog[(size_t)c * V_ + r1] = v1;
                unsigned u = ordbits(v0), w = ordbits(v1);
                cm[f * 2 + j] = (u > w) ? u : w;
            }
        }
#pragma unroll
        for (int s = 4; s <= 16; s <<= 1)
#pragma unroll
            for (int q = 0; q < 16; q++) {
                unsigned o = __shfl_xor_sync(0xffffffffu, cm[q], s);
                if (o > cm[q]) cm[q] = o;
            }
        if (lane < 4) {
#pragma unroll
            for (int f = 0; f < 8; f++)
#pragma unroll
                for (int j = 0; j < 2; j++)
                    atomicMax(&s_cmax[f * 8 + lane * 2 + j], cm[f * 2 + j]);
        }
    }
}

// gates, balanced split-K: grid (24, 6), each CTA 8 chunks of SPLITS=2 work
// y=0: gi K[0:256)  (+GcT)   y=1: gi K[256:512)  -> g_giT2
// y=2: gh K[0:256)  (+b_hh)  y=3: gh K[256:512)  -> g_ghT2
// y=4: gh K[512:768)-> g_ghT3  y=5: gh K[768:1024)-> g_ghT4
__global__ void __launch_bounds__(256) k_tc_gates(const float* __restrict__ b_hh) {
    const int m0 = blockIdx.x * 128;
    const int q = H_ / 4;   // 256
    switch (blockIdx.y) {
    case 0:
        mma_core<0, 2, 2>(g_WihE_hi, g_WihE_lo, g_x_hi, g_x_lo,
                          E_, E_ / 2, nullptr, g_GcT, g_giT, m0, nullptr);
        break;
    case 1:
        mma_core<0, 2, 2>(g_WihE_hi + E_ / 2, g_WihE_lo + E_ / 2,
                          g_x_hi + E_ / 2, g_x_lo + E_ / 2,
                          E_, E_ / 2, nullptr, nullptr, g_giT2, m0, nullptr);
        break;
    case 2:
        mma_core<0, 2, 2>(g_Whh_hi, g_Whh_lo, g_h_hi, g_h_lo,
                          H_, q, b_hh, nullptr, g_ghT, m0, nullptr);
        break;
    case 3:
        mma_core<0, 2, 2>(g_Whh_hi + q, g_Whh_lo + q, g_h_hi + q, g_h_lo + q,
                          H_, q, nullptr, nullptr, g_ghT2, m0, nullptr);
        break;
    case 4:
        mma_core<0, 2, 2>(g_Whh_hi + 2 * q, g_Whh_lo + 2 * q,
                          g_h_hi + 2 * q, g_h_lo + 2 * q,
                          H_, q, nullptr, nullptr, g_ghT3, m0, nullptr);
        break;
    default:
        mma_core<0, 2, 2>(g_Whh_hi + 3 * q, g_Whh_lo + 3 * q,
                          g_h_hi + 3 * q, g_h_lo + 3 * q,
                          H_, q, nullptr, nullptr, g_ghT4, m0, nullptr);
    }
}

// logits: 250 CTAs (~2/SM), 4-stage pipeline, fused per-batch col-max
__global__ void __launch_bounds__(256) k_tc_logits(const float* __restrict__ out_b) {
    __shared__ unsigned s_cmax[B_];
    if (threadIdx.x < B_) s_cmax[threadIdx.x] = 0u;
    mma_core<2, 1, 4>(g_Wout_hi, nullptr, g_h_hi, nullptr,
                      H_, H_, out_b, nullptr, nullptr, blockIdx.x * 128, s_cmax);
    __syncthreads();
    if (threadIdx.x < B_) atomicMax(&g_amaxv[threadIdx.x], s_cmax[threadIdx.x]);
}

// ---------------------------------------------------------------------------
__global__ void k_setup(const float* __restrict__ enc) {
    int idx = blockIdx.x * blockDim.x + threadIdx.x;
    if (idx < B_ * 2 * HENC) {
        int b = idx / (2 * HENC);
        int k = idx % (2 * HENC);
        float v = (k < HENC) ? enc[b * HENC + k]
                             : enc[B_ * HENC + b * HENC + (k - HENC)];
        g_flat[idx] = v;
    }
    if (idx < B_) { g_inp[idx] = SOS; g_fin[idx] = 0; g_amaxv[idx] = 0u; }
    if (idx < 2)  { g_nmax[idx] = 0u; }
}

__global__ void __launch_bounds__(256) k_gemm(
    const float* __restrict__ A, int lda,
    const float* __restrict__ W, int ldw, int woff, int K,
    const float* __restrict__ bias, float* __restrict__ C, int ldc)
{
    __shared__ float As[32][68];
    __shared__ float Ws[32][68];
    const int tid = threadIdx.x;
    const int tx = tid & 15, ty = tid >> 4;
    const int n0 = blockIdx.x * 64;
    float acc[4][4] = {};

    for (int k0 = 0; k0 < K; k0 += 32) {
#pragma unroll
        for (int it = 0; it < 2; it++) {
            int idx = tid + it * 256;
            int row = idx >> 3;
            int kq  = (idx & 7) << 2;
            float4 v = *(const float4*)(A + (size_t)row * lda + k0 + kq);
            As[kq][row] = v.x; As[kq + 1][row] = v.y;
            As[kq + 2][row] = v.z; As[kq + 3][row] = v.w;
            float4 u = *(const float4*)(W + (size_t)(n0 + row) * ldw + woff + k0 + kq);
            Ws[kq][row] = u.x; Ws[kq + 1][row] = u.y;
            Ws[kq + 2][row] = u.z; Ws[kq + 3][row] = u.w;
        }
        __syncthreads();
#pragma unroll
        for (int k = 0; k < 32; k++) {
            float4 a = *(const float4*)&As[k][ty << 2];
            float4 w = *(const float4*)&Ws[k][tx << 2];
            acc[0][0] += a.x * w.x; acc[0][1] += a.x * w.y; acc[0][2] += a.x * w.z; acc[0][3] += a.x * w.w;
            acc[1][0] += a.y * w.x; acc[1][1] += a.y * w.y; acc[1][2] += a.y * w.z; acc[1][3] += a.y * w.w;
            acc[2][0] += a.z * w.x; acc[2][1] += a.z * w.y; acc[2][2] += a.z * w.z; acc[2][3] += a.z * w.w;
            acc[3][0] += a.w * w.x; acc[3][1] += a.w * w.y; acc[3][2] += a.w * w.z; acc[3][3] += a.w * w.w;
        }
        __syncthreads();
    }
#pragma unroll
    for (int i = 0; i < 4; i++) {
        int row = (ty << 2) + i;
#pragma unroll
        for (int j = 0; j < 4; j++) {
            int col = n0 + (tx << 2) + j;
            float v = acc[i][j];
            if (bias) v += bias[col];
            C[(size_t)row * ldc + col] = v;
        }
    }
}

__global__ void k_splitw(const float* __restrict__ src, int ld, int coloff, int cols,
                         __nv_bfloat16* __restrict__ hi, __nv_bfloat16* __restrict__ lo,
                         int n)
{
    int idx = blockIdx.x * blockDim.x + threadIdx.x;
    if (idx >= n) return;
    int r = idx / cols, c = idx % cols;
    float v = src[(size_t)r * ld + coloff + c];
    __nv_bfloat16 h = __float2bfloat16(v);
    hi[idx] = h;
    if (lo) lo[idx] = __float2bfloat16(v - __bfloat162float(h));
}

__global__ void k_split_h0() {
    int idx = blockIdx.x * blockDim.x + threadIdx.x;
    if (idx >= B_ * H_) return;
    float v = g_h[idx];
    __nv_bfloat16 h = __float2bfloat16(v);
    g_h_hi[idx] = h;
    g_h_lo[idx] = __float2bfloat16(v - __bfloat162float(h));
}

__global__ void k_mk_gcT() {
    int idx = blockIdx.x * blockDim.x + threadIdx.x;
    if (idx >= 3 * H_ * B_) return;
    int r = idx >> 6, c = idx & 63;
    g_GcT[idx] = g_Gc[(size_t)c * (3 * H_) + r];
}

__global__ void k_wnorms(const float* __restrict__ out_w) {
    int r = blockIdx.x * 8 + (threadIdx.x >> 5);
    int lane = threadIdx.x & 31;
    if (r >= V_) return;
    float sh = 0.f, sl = 0.f;
    for (int k = lane; k < H_; k += 32) {
        float w  = out_w[(size_t)r * H_ + k];
        float wh = __bfloat162float(g_Wout_hi[(size_t)r * H_ + k]);
        float wl = w - wh;
        sh += wh * wh;
        sl += wl * wl;
    }
#pragma unroll
    for (int s = 16; s > 0; s >>= 1) {
        sh += __shfl_xor_sync(0xffffffffu, sh, s);
        sl += __shfl_xor_sync(0xffffffffu, sl, s);
    }
    if (lane == 0) {
        atomicMax(&g_nmax[0], __float_as_uint(sqrtf(sh)));
        atomicMax(&g_nmax[1], __float_as_uint(sqrtf(sl)));
    }
}

// initial x split (SOS) + hnorm reset — pre-loop only
__global__ void k_split_x(const float* __restrict__ emb) {
    int idx = blockIdx.x * blockDim.x + threadIdx.x;
    if (idx < 2 * B_) g_hnorm[idx] = 0.f;
    if (idx >= B_ * E_) return;
    int b = idx >> 9;
    int k = idx & (E_ - 1);
    float v = emb[(size_t)g_inp[b] * E_ + k];
    __nv_bfloat16 h = __float2bfloat16(v);
    g_x_hi[idx] = h;
    g_x_lo[idx] = __float2bfloat16(v - __bfloat162float(h));
}

// GRU gates (summing split-K partials) + h split + per-batch norms
__global__ void __launch_bounds__(256) k_gates2() {
    __shared__ float sb1[B_], sb2[B_];
    int tid = threadIdx.x;
    if (tid < B_) { sb1[tid] = 0.f; sb2[tid] = 0.f; }
    __syncthreads();

    int idx = blockIdx.x * 256 + tid;
    int b = idx & (B_ - 1);
    int i = idx >> 6;
    size_t o0 = (size_t)i * 64 + b;
    size_t o1 = (size_t)(H_ + i) * 64 + b;
    size_t o2 = (size_t)(2 * H_ + i) * 64 + b;
    float ir  = g_giT[o0] + g_giT2[o0];
    float iz  = g_giT[o1] + g_giT2[o1];
    float in_ = g_giT[o2] + g_giT2[o2];
    float hr  = g_ghT[o0] + g_ghT2[o0] + g_ghT3[o0] + g_ghT4[o0];
    float hz  = g_ghT[o1] + g_ghT2[o1] + g_ghT3[o1] + g_ghT4[o1];
    float hn  = g_ghT[o2] + g_ghT2[o2] + g_ghT3[o2] + g_ghT4[o2];
    float r = 1.f / (1.f + expf(-(ir + hr)));
    float z = 1.f / (1.f + expf(-(iz + hz)));
    float n = tanhf(in_ + r * hn);
    size_t hidx = (size_t)b * H_ + i;
    float h = g_h[hidx];
    float hnew = (1.f - z) * n + z * h;
    g_h[hidx] = hnew;
    __nv_bfloat16 hh = __float2bfloat16(hnew);
    g_h_hi[hidx] = hh;
    float res = hnew - __bfloat162float(hh);
    g_h_lo[hidx] = __float2bfloat16(res);

    atomicAdd(&sb1[b], hnew * hnew);
    atomicAdd(&sb2[b], res * res);
    __syncthreads();
    if (tid < B_) {
        atomicAdd(&g_hnorm[tid],      sb1[tid]);
        atomicAdd(&g_hnorm[B_ + tid], sb2[tid]);
    }
}

// ---------------------------------------------------------------------------
// Rescore: per-batch bound (fused g_amaxv), exact fp32 rescore,
// full-scan fallback, fused next-x embed split + per-step resets.
// ---------------------------------------------------------------------------
__global__ void __launch_bounds__(256) k_rescore(
    const float* __restrict__ out_w, const float* __restrict__ out_b,
    const float* __restrict__ emb, float* __restrict__ out_tok, int t)
{
    __shared__ float sh_h[H_];
    __shared__ int cand[CAND_CAP];
    __shared__ int cnt;
    __shared__ unsigned long long bestkey;
    __shared__ int s_tok;

    const int b = blockIdx.x;
    const int tid = threadIdx.x, lane = tid & 31, warp = tid >> 5;
    const float* ap = g_applog + (size_t)b * V_;

    for (int i = tid; i < H_; i += 256) sh_h[i] = g_h[(size_t)b * H_ + i];
    if (tid == 0) { cnt = 0; bestkey = 0ULL; }
    __syncthreads();

    const float A   = ordfloat(g_amaxv[b]);
    const float nh  = sqrtf(g_hnorm[b]);
    const float nhl = sqrtf(g_hnorm[B_ + b]);
    const float nwh = __uint_as_float(g_nmax[0]);
    const float nwl = __uint_as_float(g_nmax[1]);
    const float eps = 2.f * (nwl * nh + nwh * nhl) + 0.1f;
    const float thresh = A - eps;

    for (int r = tid; r < V_; r += 256) {
        if (ap[r] >= thresh) {
            int i = atomicAdd(&cnt, 1);
            if (i < CAND_CAP) cand[i] = r;
        }
    }
    __syncthreads();

    if (cnt <= CAND_CAP) {
        const int nc = cnt;
        for (int ci = warp; ci < nc; ci += 8) {
            const int r = cand[ci];
            float s = 0.f;
            for (int k = lane; k < H_; k += 32)
                s += out_w[(size_t)r * H_ + k] * sh_h[k];
#pragma unroll
            for (int sft = 16; sft > 0; sft >>= 1)
                s += __shfl_xor_sync(0xffffffffu, s, sft);
            if (lane == 0)
                atomicMax(&bestkey, packkey(s + out_b[r], r));
        }
    } else {
        for (int r = warp; r < V_; r += 8) {
            float s = 0.f;
            for (int k = lane; k < H_; k += 32)
                s += out_w[(size_t)r * H_ + k] * sh_h[k];
#pragma unroll
            for (int sft = 16; sft > 0; sft >>= 1)
                s += __shfl_xor_sync(0xffffffffu, s, sft);
            if (lane == 0)
                atomicMax(&bestkey, packkey(s + out_b[r], r));
        }
    }
    __syncthreads();

    if (tid == 0) {
        int tok = (int)(0xFFFFFFFFu - (unsigned)(bestkey & 0xFFFFFFFFull));
        out_tok[b * T_ + t] = (float)tok;
        int fin = g_fin[b] | (tok == EOS);
        g_fin[b] = fin;
        int ninp = fin ? EOS : tok;
        g_inp[b] = ninp;
        s_tok = ninp;
        g_amaxv[b] = 0u;
    }
    __syncthreads();

    const int ninp = s_tok;
    for (int k = tid; k < E_; k += 256) {
        float v = emb[(size_t)ninp * E_ + k];
        __nv_bfloat16 h = __float2bfloat16(v);
        g_x_hi[b * E_ + k] = h;
        g_x_lo[b * E_ + k] = __float2bfloat16(v - __bfloat162float(h));
    }
    if (tid < 2) g_hnorm[tid * B_ + b] = 0.f;
}

__global__ void k_writeh(float* __restrict__ out_h) {
    int idx = blockIdx.x * blockDim.x + threadIdx.x;
    if (idx < B_ * H_) out_h[idx] = g_h[idx];
}

// ---------------------------------------------------------------------------
extern "C" void kernel_launch(void* const* d_in, const int* in_sizes, int n_in,
                              void* d_out, int out_size) {
    const float* enc   = (const float*)d_in[0];
    const float* emb   = (const float*)d_in[1];
    const float* Wh_w  = (const float*)d_in[2];
    const float* Wh_b  = (const float*)d_in[3];
    const float* W_ih  = (const float*)d_in[4];
    const float* W_hh  = (const float*)d_in[5];
    const float* b_ih  = (const float*)d_in[6];
    const float* b_hh  = (const float*)d_in[7];
    const float* out_w = (const float*)d_in[8];
    const float* out_b = (const float*)d_in[9];
    float* out = (float*)d_out;

    void* pv;
    cudaGetSymbolAddress(&pv, g_flat);     float* f_flat = (float*)pv;
    cudaGetSymbolAddress(&pv, g_h);        float* f_h    = (float*)pv;
    cudaGetSymbolAddress(&pv, g_Gc);       float* f_Gc   = (float*)pv;
    cudaGetSymbolAddress(&pv, g_WihE_hi);  __nv_bfloat16* w_ihe_h = (__nv_bfloat16*)pv;
    cudaGetSymbolAddress(&pv, g_WihE_lo);  __nv_bfloat16* w_ihe_l = (__nv_bfloat16*)pv;
    cudaGetSymbolAddress(&pv, g_Whh_hi);   __nv_bfloat16* w_hh_h  = (__nv_bfloat16*)pv;
    cudaGetSymbolAddress(&pv, g_Whh_lo);   __nv_bfloat16* w_hh_l  = (__nv_bfloat16*)pv;
    cudaGetSymbolAddress(&pv, g_Wout_hi);  __nv_bfloat16* w_o_h   = (__nv_bfloat16*)pv;

    cudaFuncSetAttribute(k_tc_gates,  cudaFuncAttributeMaxDynamicSharedMemorySize, TCSMEM_GATES);
    cudaFuncSetAttribute(k_tc_logits, cudaFuncAttributeMaxDynamicSharedMemorySize, TCSMEM_LOGITS);

    // ---- one-time setup ----
    k_setup<<<256, 256>>>(enc);
    k_gemm<<<H_ / 64, 256>>>(f_flat, 2 * HENC, Wh_w, 2 * HENC, 0, 2 * HENC, Wh_b, f_h, H_);
    k_gemm<<<3 * H_ / 64, 256>>>(f_flat, 2 * HENC, W_ih, E_ + 2 * HENC, E_, 2 * HENC,
                                 b_ih, f_Gc, 3 * H_);
    k_split_h0<<<(B_ * H_) / 256, 256>>>();
    k_mk_gcT<<<(3 * H_ * B_) / 256, 256>>>();
    k_splitw<<<(3 * H_ * E_) / 256, 256>>>(W_ih, E_ + 2 * HENC, 0, E_,
                                           w_ihe_h, w_ihe_l, 3 * H_ * E_);
    k_splitw<<<(3 * H_ * H_) / 256, 256>>>(W_hh, H_, 0, H_,
                                           w_hh_h, w_hh_l, 3 * H_ * H_);
    k_splitw<<<(V_ * H_) / 256, 256>>>(out_w, H_, 0, H_,
                                       w_o_h, nullptr, V_ * H_);
    k_wnorms<<<V_ / 8, 256>>>(out_w);
    k_split_x<<<(B_ * E_) / 256, 256>>>(emb);

    // ---- decode loop (4 kernels/step) ----
    dim3 ggates(3 * H_ / 128, 6);
    for (int t = 0; t < T_; t++) {
        k_tc_gates<<<ggates, 256, TCSMEM_GATES>>>(b_hh);
        k_gates2<<<(B_ * H_) / 256, 256>>>();
        k_tc_logits<<<V_ / 128, 256, TCSMEM_LOGITS>>>(out_b);
        k_rescore<<<B_, 256>>>(out_w, out_b, emb, out, t);
    }

    if (out_size >= B_ * T_ + B_ * H_)
        k_writeh<<<(B_ * H_) / 256, 256>>>(out + B_ * T_);
}